// round 7
// baseline (speedup 1.0000x reference)
#include <cuda_runtime.h>
#include <cstdint>

// ----------------------------------------------------------------------------
// MultiheadAttention forward — 1xTF32, vectorized-LDS (k/n-permuted) GEMMs.
//   prep    : round weights + inputs to tf32; pack biases
//   proj    : fused z=3 launch, Q/K/V projections, outputs rounded
//   scores  : per (b,h) S = Q K^T / 8 (raw fp32)
//   softmax : block per (b,q), aw rounded to tf32 on store
//   context : split-K=2, partials; addhalves reduces + rounds ctx
//   outproj : BN=64, cv = ctx @ Wo + bo
// GEMM inner loop: LDS.128 quad loads with consistent k-permutation (A<->B)
// and, for NN, n-permutation undone in the epilogue. 2-stage, 2 CTAs/SM.
// ----------------------------------------------------------------------------

#define NEG_INF_F (__int_as_float(0xff7fffff))   // -FLT_MAX

static __device__ float g_qkv[3 * 2048 * 1024];   // rounded Q,K,V projections
static __device__ float g_rin[3 * 2048 * 1024];   // rounded inputs q,k,v
static __device__ float g_w  [3 * 1024 * 1024];   // rounded Wq,Wk,Wv
static __device__ float g_wo [1024 * 1024];       // rounded Wo
static __device__ float g_b3 [3 * 1024];          // packed biases bq,bk,bv
static __device__ float g_ctx[2048 * 1024];
static __device__ float g_cp [2 * 2048 * 1024];   // split-K partials

__device__ __forceinline__ uint32_t f2tf(float x) {
    uint32_t r;
    asm("cvt.rna.tf32.f32 %0, %1;" : "=r"(r) : "f"(x));
    return r;
}
__device__ __forceinline__ uint32_t s2u(const void* p) {
    return (uint32_t)__cvta_generic_to_shared(p);
}

#define CP_ASYNC16(dst, src) \
    asm volatile("cp.async.cg.shared.global [%0], [%1], 16;" :: "r"(dst), "l"(src))
#define CP_COMMIT() asm volatile("cp.async.commit_group;")
#define CP_WAIT0()  asm volatile("cp.async.wait_group 0;")

__device__ __forceinline__ void mma8(float c[4], uint32_t a0, uint32_t a1,
                                     uint32_t a2, uint32_t a3,
                                     uint32_t b0, uint32_t b1) {
    asm volatile(
        "mma.sync.aligned.m16n8k8.row.col.f32.tf32.tf32.f32 "
        "{%0,%1,%2,%3},{%4,%5,%6,%7},{%8,%9},{%0,%1,%2,%3};"
        : "+f"(c[0]), "+f"(c[1]), "+f"(c[2]), "+f"(c[3])
        : "r"(a0), "r"(a1), "r"(a2), "r"(a3), "r"(b0), "r"(b1));
}

#define R4V(v) v.x = __uint_as_float(f2tf(v.x)); v.y = __uint_as_float(f2tf(v.y)); \
               v.z = __uint_as_float(f2tf(v.z)); v.w = __uint_as_float(f2tf(v.w));

__global__ __launch_bounds__(256) void round_w4(
    const float* __restrict__ a, const float* __restrict__ b,
    const float* __restrict__ c, const float* __restrict__ d,
    float* __restrict__ oa, float* __restrict__ ob,
    float* __restrict__ oc, float* __restrict__ od)
{
    int i = blockIdx.x * 256 + threadIdx.x;
    float4 va = ((const float4*)a)[i]; R4V(va) ((float4*)oa)[i] = va;
    float4 vb = ((const float4*)b)[i]; R4V(vb) ((float4*)ob)[i] = vb;
    float4 vc = ((const float4*)c)[i]; R4V(vc) ((float4*)oc)[i] = vc;
    float4 vd = ((const float4*)d)[i]; R4V(vd) ((float4*)od)[i] = vd;
}

__global__ __launch_bounds__(256) void round_in3(
    const float* __restrict__ a, const float* __restrict__ b,
    const float* __restrict__ c,
    float* __restrict__ oa, float* __restrict__ ob, float* __restrict__ oc)
{
    int i = blockIdx.x * 256 + threadIdx.x;
    float4 va = ((const float4*)a)[i]; R4V(va) ((float4*)oa)[i] = va;
    float4 vb = ((const float4*)b)[i]; R4V(vb) ((float4*)ob)[i] = vb;
    float4 vc = ((const float4*)c)[i]; R4V(vc) ((float4*)oc)[i] = vc;
}

__global__ __launch_bounds__(256) void packb(
    const float* __restrict__ a, const float* __restrict__ b,
    const float* __restrict__ c, float* __restrict__ out)
{
    int i = blockIdx.x * 256 + threadIdx.x;         // < 3072
    int sel = i >> 10;
    const float* p = sel == 0 ? a : (sel == 1 ? b : c);
    out[i] = p[i & 1023];
}

// C = scale*A*op(B) + bias[bb*biasStride + col].
// NT=false: B [K,N] row-major (NN); NT=true: B [N,K] row-major (C = A B^T).
// z -> (s = z/ZBH, r = z%ZBH, bb = r/H, hh = r%H); s adds split-K offsets.
// All A/B operand data must already be tf32-rounded.
template <int BM, int BN, bool NT, int NTHREADS, bool ROUND>
__global__ __launch_bounds__(NTHREADS, 2) void gemmv(
    const float* __restrict__ A, long long aB, long long aH, long long aS, int lda,
    const float* __restrict__ Bmat, long long bB, long long bH, long long bS, int ldb,
    float* __restrict__ C, long long cB, long long cH, long long cS, int ldc,
    int K, const float* __restrict__ bias, long long biasStride,
    float scale, int H, int ZBH)
{
    constexpr int BK = 32;
    constexpr int WARPS_M = BM / 64;          // warp tile 64x32
    constexpr int AP  = 48;                   // padded row (floats), LDS.128-safe
    constexpr int ASZ = BM * AP;
    constexpr int BSZ = NT ? BN * AP : BK * BN;   // NN: XOR-swizzled, no pad

    extern __shared__ float sm[];
    float* sA = sm;
    float* sB = sm + 2 * ASZ;

    const int z  = blockIdx.z;
    const int s  = z / ZBH;
    const int r0 = z - s * ZBH;
    const int bb = r0 / H, hh = r0 - bb * H;
    const float* Ap = A + (long long)bb * aB + (long long)hh * aH + (long long)s * aS
                        + (long long)blockIdx.y * BM * lda;
    const float* Bp;
    if (NT) Bp = Bmat + (long long)bb * bB + (long long)hh * bH + (long long)s * bS
                      + (long long)blockIdx.x * BN * ldb;
    else    Bp = Bmat + (long long)bb * bB + (long long)hh * bH + (long long)s * bS
                      + (long long)blockIdx.x * BN;
    float* Cp = C + (long long)bb * cB + (long long)hh * cH + (long long)s * cS;
    const float* bp = bias ? bias + (long long)bb * biasStride : nullptr;

    const int tid  = threadIdx.x;
    const int lane = tid & 31;
    const int wid  = tid >> 5;
    const int wm   = (wid % WARPS_M) * 64;
    const int wn   = (wid / WARPS_M) * 32;
    const int lq   = lane >> 2;               // 0..7
    const int lc   = lane & 3;                // 0..3 (k-quad index)

    float acc[4][4][4];                       // [mt][nt or i][4]
#pragma unroll
    for (int i = 0; i < 4; i++)
#pragma unroll
        for (int j = 0; j < 4; j++)
#pragma unroll
            for (int c = 0; c < 4; c++) acc[i][j][c] = 0.f;

    auto load_tile = [&](int slot, int k0) {
        float* dA = sA + slot * ASZ;
        float* dB = sB + slot * BSZ;
#pragma unroll
        for (int i = 0; i < (BM * 8) / NTHREADS; i++) {
            int t = tid + i * NTHREADS;
            int r = t >> 3, cq = t & 7;
            CP_ASYNC16(s2u(dA + r * AP + cq * 4),
                       Ap + (long long)r * lda + k0 + cq * 4);
        }
        if (NT) {
#pragma unroll
            for (int i = 0; i < (BN * 8) / NTHREADS; i++) {
                int t = tid + i * NTHREADS;
                int r = t >> 3, cq = t & 7;
                CP_ASYNC16(s2u(dB + r * AP + cq * 4),
                           Bp + (long long)r * ldb + k0 + cq * 4);
            }
        } else {
#pragma unroll
            for (int i = 0; i < (BK * BN / 4) / NTHREADS; i++) {
                int t = tid + i * NTHREADS;
                constexpr int C4 = BN / 4;
                int r = t / C4, cq = t - r * C4;
                int phys = cq ^ (((r >> 2) & 7) << 1);
                CP_ASYNC16(s2u(dB + r * BN + phys * 4),
                           Bp + (long long)(k0 + r) * ldb + cq * 4);
            }
        }
    };

    auto compute = [&](int slot) {
        const float* cA = sA + slot * ASZ;
        const float* cB = sB + slot * BSZ;
#pragma unroll
        for (int half = 0; half < 2; half++) {
            const int kb = half * 16;
            uint4 a1[4], a2[4];
#pragma unroll
            for (int mt = 0; mt < 4; mt++) {
                int r = wm + mt * 16 + lq;
                a1[mt] = *(const uint4*)(cA + r * AP + kb + lc * 4);
                a2[mt] = *(const uint4*)(cA + (r + 8) * AP + kb + lc * 4);
            }
            if (NT) {
                uint4 bq[4];
#pragma unroll
                for (int nt = 0; nt < 4; nt++) {
                    int n = wn + nt * 8 + lq;
                    bq[nt] = *(const uint4*)(cB + n * AP + kb + lc * 4);
                }
#pragma unroll
                for (int mt = 0; mt < 4; mt++)
#pragma unroll
                    for (int nt = 0; nt < 4; nt++) {
                        mma8(acc[mt][nt], a1[mt].x, a2[mt].x, a1[mt].y, a2[mt].y,
                             bq[nt].x, bq[nt].y);
                        mma8(acc[mt][nt], a1[mt].z, a2[mt].z, a1[mt].w, a2[mt].w,
                             bq[nt].z, bq[nt].w);
                    }
            } else {
                uint4 bq[4];
#pragma unroll
                for (int j = 0; j < 4; j++) {
                    int row  = kb + lc * 4 + j;
                    int nq   = (wn >> 2) + lq;
                    int phys = nq ^ (((row >> 2) & 7) << 1);
                    bq[j] = *(const uint4*)(cB + row * BN + phys * 4);
                }
#pragma unroll
                for (int mt = 0; mt < 4; mt++) {
                    mma8(acc[mt][0], a1[mt].x, a2[mt].x, a1[mt].y, a2[mt].y,
                         bq[0].x, bq[1].x);
                    mma8(acc[mt][0], a1[mt].z, a2[mt].z, a1[mt].w, a2[mt].w,
                         bq[2].x, bq[3].x);
                    mma8(acc[mt][1], a1[mt].x, a2[mt].x, a1[mt].y, a2[mt].y,
                         bq[0].y, bq[1].y);
                    mma8(acc[mt][1], a1[mt].z, a2[mt].z, a1[mt].w, a2[mt].w,
                         bq[2].y, bq[3].y);
                    mma8(acc[mt][2], a1[mt].x, a2[mt].x, a1[mt].y, a2[mt].y,
                         bq[0].z, bq[1].z);
                    mma8(acc[mt][2], a1[mt].z, a2[mt].z, a1[mt].w, a2[mt].w,
                         bq[2].z, bq[3].z);
                    mma8(acc[mt][3], a1[mt].x, a2[mt].x, a1[mt].y, a2[mt].y,
                         bq[0].w, bq[1].w);
                    mma8(acc[mt][3], a1[mt].z, a2[mt].z, a1[mt].w, a2[mt].w,
                         bq[2].w, bq[3].w);
                }
            }
        }
    };

    const int kt_n = K / BK;
    load_tile(0, 0);
    CP_COMMIT();
    for (int kt = 0; kt < kt_n; kt++) {
        CP_WAIT0();
        __syncthreads();
        int nk = kt + 1;
        if (nk < kt_n) load_tile(nk & 1, nk * BK);
        CP_COMMIT();
        compute(kt & 1);
    }

    const int row0 = blockIdx.y * BM + wm;
    const int col0 = blockIdx.x * BN + wn;
    if (NT) {
#pragma unroll
        for (int mt = 0; mt < 4; mt++)
#pragma unroll
            for (int nt = 0; nt < 4; nt++) {
                int r = row0 + mt * 16 + lq;
                int c = col0 + nt * 8 + 2 * lc;
                float b0 = bp ? bp[c]     : 0.f;
                float b1 = bp ? bp[c + 1] : 0.f;
                float o0 = acc[mt][nt][0] * scale + b0;
                float o1 = acc[mt][nt][1] * scale + b1;
                float o2 = acc[mt][nt][2] * scale + b0;
                float o3 = acc[mt][nt][3] * scale + b1;
                if (ROUND) {
                    o0 = __uint_as_float(f2tf(o0));
                    o1 = __uint_as_float(f2tf(o1));
                    o2 = __uint_as_float(f2tf(o2));
                    o3 = __uint_as_float(f2tf(o3));
                }
                *(float2*)(Cp + (long long)r * ldc + c)       = make_float2(o0, o1);
                *(float2*)(Cp + (long long)(r + 8) * ldc + c) = make_float2(o2, o3);
            }
    } else {
        // n-permuted: acc[mt][i] -> cols 8*lc+i and 8*lc+4+i
#pragma unroll
        for (int mt = 0; mt < 4; mt++)
#pragma unroll
            for (int i = 0; i < 4; i++) {
                int r  = row0 + mt * 16 + lq;
                int c0 = col0 + 8 * lc + i;
                int c1 = c0 + 4;
                float b0 = bp ? bp[c0] : 0.f;
                float b1 = bp ? bp[c1] : 0.f;
                float o0 = acc[mt][i][0] * scale + b0;
                float o1 = acc[mt][i][1] * scale + b1;
                float o2 = acc[mt][i][2] * scale + b0;
                float o3 = acc[mt][i][3] * scale + b1;
                if (ROUND) {
                    o0 = __uint_as_float(f2tf(o0));
                    o1 = __uint_as_float(f2tf(o1));
                    o2 = __uint_as_float(f2tf(o2));
                    o3 = __uint_as_float(f2tf(o3));
                }
                Cp[(long long)r * ldc + c0]       = o0;
                Cp[(long long)r * ldc + c1]       = o1;
                Cp[(long long)(r + 8) * ldc + c0] = o2;
                Cp[(long long)(r + 8) * ldc + c1] = o3;
            }
    }
}

// Block = one (b,q); mask row in smem; 16 warps = 16 heads.
// aw rounded to tf32 on store (it is the context GEMM's A operand).
__global__ __launch_bounds__(512) void softmax_rows(
    float* __restrict__ aw, const int* __restrict__ mask)
{
    __shared__ int smask[1024];
    const int bq = blockIdx.x;                 // b*1024 + q
    const int b  = bq >> 10, q = bq & 1023;
    const int* mrow = mask + ((long long)bq << 10);
    if (threadIdx.x < 256)
        ((int4*)smask)[threadIdx.x] = ((const int4*)mrow)[threadIdx.x];
    __syncthreads();

    const int h    = threadIdx.x >> 5;
    const int lane = threadIdx.x & 31;
    float* arow = aw + ((long long)((b * 16 + h) * 1024 + q) << 10);

    float v[32];
    float m = NEG_INF_F;
#pragma unroll
    for (int j = 0; j < 8; j++) {
        int c = (lane + 32 * j) * 4;
        float4 f = __ldcs((const float4*)(arow + c));
        int4  mk = *(const int4*)(smask + c);
        v[4 * j + 0] = mk.x ? f.x : NEG_INF_F;
        v[4 * j + 1] = mk.y ? f.y : NEG_INF_F;
        v[4 * j + 2] = mk.z ? f.z : NEG_INF_F;
        v[4 * j + 3] = mk.w ? f.w : NEG_INF_F;
        m = fmaxf(m, fmaxf(fmaxf(v[4 * j], v[4 * j + 1]),
                           fmaxf(v[4 * j + 2], v[4 * j + 3])));
    }
#pragma unroll
    for (int o = 16; o > 0; o >>= 1) m = fmaxf(m, __shfl_xor_sync(0xffffffffu, m, o));
    float s = 0.f;
#pragma unroll
    for (int i = 0; i < 32; i++) { float e = __expf(v[i] - m); v[i] = e; s += e; }
#pragma unroll
    for (int o = 16; o > 0; o >>= 1) s += __shfl_xor_sync(0xffffffffu, s, o);
    float inv = 1.f / s;
#pragma unroll
    for (int j = 0; j < 8; j++) {
        int c = (lane + 32 * j) * 4;
        float4 o4 = make_float4(v[4 * j] * inv, v[4 * j + 1] * inv,
                                v[4 * j + 2] * inv, v[4 * j + 3] * inv);
        R4V(o4)
        __stcs((float4*)(arow + c), o4);
    }
}

// ctx = round_tf32(partial0 + partial1), 2M floats (grid 2048x256).
__global__ __launch_bounds__(256) void addhalves(
    const float* __restrict__ p, float* __restrict__ ctx)
{
    int i = blockIdx.x * 256 + threadIdx.x;
    float4 a = ((const float4*)p)[i];
    float4 b = ((const float4*)(p + 2097152))[i];
    float4 o = make_float4(a.x + b.x, a.y + b.y, a.z + b.z, a.w + b.w);
    R4V(o)
    ((float4*)ctx)[i] = o;
}

extern "C" void kernel_launch(void* const* d_in, const int* in_sizes, int n_in,
                              void* d_out, int out_size)
{
    const float* key   = (const float*)d_in[0];
    const float* value = (const float*)d_in[1];
    const float* query = (const float*)d_in[2];
    const int*   mask  = (const int*)d_in[3];
    const float* Wk = (const float*)d_in[4];
    const float* bk = (const float*)d_in[5];
    const float* Wv = (const float*)d_in[6];
    const float* bv = (const float*)d_in[7];
    const float* Wq = (const float*)d_in[8];
    const float* bq = (const float*)d_in[9];
    const float* Wo = (const float*)d_in[10];
    const float* bo = (const float*)d_in[11];

    float* cv = (float*)d_out;                    // [2, 1024, 1024]
    float* aw = cv + 2LL * 1024 * 1024;           // [2, 16, 1024, 1024]

    float *qkv, *rin, *w3, *wo3, *b3, *gc, *gp;
    cudaGetSymbolAddress((void**)&qkv, g_qkv);
    cudaGetSymbolAddress((void**)&rin, g_rin);
    cudaGetSymbolAddress((void**)&w3,  g_w);
    cudaGetSymbolAddress((void**)&wo3, g_wo);
    cudaGetSymbolAddress((void**)&b3,  g_b3);
    cudaGetSymbolAddress((void**)&gc,  g_ctx);
    cudaGetSymbolAddress((void**)&gp,  g_cp);

    // smem: NN128 = 2*(128*48 + 32*128)*4 = 81920
    //       NT128 = 2*(128*48 + 128*48)*4 = 98304
    //       NN64  = 2*(128*48 + 32*64)*4  = 65536
    cudaFuncSetAttribute((const void*)gemmv<128, 128, false, 256, true>,
                         cudaFuncAttributeMaxDynamicSharedMemorySize, 81920);
    cudaFuncSetAttribute((const void*)gemmv<128, 128, true, 256, false>,
                         cudaFuncAttributeMaxDynamicSharedMemorySize, 98304);
    cudaFuncSetAttribute((const void*)gemmv<128, 64, false, 128, false>,
                         cudaFuncAttributeMaxDynamicSharedMemorySize, 65536);

    const long long M2 = 2097152, M1 = 1048576;
    float* Qp = qkv;              // [2048,1024] rounded Q
    float* Kp = qkv + M2;         // [2048,1024] rounded K
    float* Vp = qkv + 2 * M2;     // [2048,1024] rounded V

    // 0) prep
    round_w4<<<1024, 256>>>(Wq, Wk, Wv, Wo, w3, w3 + M1, w3 + 2 * M1, wo3);
    round_in3<<<2048, 256>>>(query, key, value, rin, rin + M2, rin + 2 * M2);
    packb<<<12, 256>>>(bq, bk, bv, b3);

    // 1) fused projections: z=0,1,2 -> Q,K,V (outputs tf32-rounded)
    gemmv<128, 128, false, 256, true><<<dim3(8, 16, 3), 256, 81920>>>(
        rin, M2, 0, 0, 1024,
        w3,  M1, 0, 0, 1024,
        qkv, M2, 0, 0, 1024,
        1024, b3, 1024, 1.f, 1, 3);

    // 2) scores per (b,h): S = Q K^T / 8 -> aw raw fp32
    gemmv<128, 128, true, 256, false><<<dim3(8, 8, 32), 256, 98304>>>(
        Qp, M1, 64, 0, 1024,
        Kp, M1, 64, 0, 1024,
        aw, 16777216LL, 1048576LL, 0, 1024,
        64, nullptr, 0, 0.125f, 16, 32);

    // 3) masked softmax (block per (b,q)); aw rounded to tf32
    softmax_rows<<<2048, 512>>>(aw, mask);

    // 4) context per (b,h), split-K=2 -> partials, then reduce (+round ctx)
    gemmv<128, 64, false, 128, false><<<dim3(1, 8, 64), 128, 65536>>>(
        aw, 16777216LL, 1048576LL, 512, 1024,
        Vp, M1, 64, 512LL * 1024, 1024,
        gp, M1, 64, M2, 1024,
        512, nullptr, 0, 1.f, 16, 32);
    addhalves<<<2048, 256>>>(gp, gc);

    // 5) output projection: cv = ctx @ Wo + bo  (BN=64, grid 256)
    gemmv<128, 64, false, 128, false><<<dim3(16, 16, 1), 128, 65536>>>(
        gc,  0, 0, 0, 1024,
        wo3, 0, 0, 0, 1024,
        cv,  0, 0, 0, 1024,
        1024, bo, 0, 1.f, 1, 1);
}

// round 9
// speedup vs baseline: 1.2417x; 1.2417x over previous
#include <cuda_runtime.h>
#include <cstdint>

// ----------------------------------------------------------------------------
// MultiheadAttention forward — 1xTF32, R6 structure + k-pair float2 fragments.
//   prep    : round weights + inputs to tf32; pack biases
//   proj    : fused z=3 launch, Q/K/V projections, outputs rounded
//   scores  : per (b,h) S = Q K^T / 8 (raw fp32), 2-stage
//   softmax : block per (b,q), aw rounded to tf32 on store
//   context : per (b,h) ctx = aw @ V (full K, rounded epilogue)
//   outproj : BN=64, cv = ctx @ Wo + bo
// k-pair trick: thread's two k-slots = {kb+2lc, kb+2lc+1} (adjacent) on BOTH
// A and B -> LDS.64 fragment loads, conflict-free at AP=40. Same math.
// ----------------------------------------------------------------------------

#define NEG_INF_F (__int_as_float(0xff7fffff))   // -FLT_MAX

static __device__ float g_qkv[3 * 2048 * 1024];   // rounded Q,K,V projections
static __device__ float g_rin[3 * 2048 * 1024];   // rounded inputs q,k,v
static __device__ float g_w  [3 * 1024 * 1024];   // rounded Wq,Wk,Wv
static __device__ float g_wo [1024 * 1024];       // rounded Wo
static __device__ float g_b3 [3 * 1024];          // packed biases bq,bk,bv
static __device__ float g_ctx[2048 * 1024];

__device__ __forceinline__ uint32_t f2tf(float x) {
    uint32_t r;
    asm("cvt.rna.tf32.f32 %0, %1;" : "=r"(r) : "f"(x));
    return r;
}
__device__ __forceinline__ uint32_t s2u(const void* p) {
    return (uint32_t)__cvta_generic_to_shared(p);
}

#define CP_ASYNC16(dst, src) \
    asm volatile("cp.async.cg.shared.global [%0], [%1], 16;" :: "r"(dst), "l"(src))
#define CP_COMMIT() asm volatile("cp.async.commit_group;")
template <int N>
__device__ __forceinline__ void cp_wait() {
    asm volatile("cp.async.wait_group %0;" :: "n"(N));
}

__device__ __forceinline__ void mma8(float c[4], uint32_t a0, uint32_t a1,
                                     uint32_t a2, uint32_t a3,
                                     uint32_t b0, uint32_t b1) {
    asm volatile(
        "mma.sync.aligned.m16n8k8.row.col.f32.tf32.tf32.f32 "
        "{%0,%1,%2,%3},{%4,%5,%6,%7},{%8,%9},{%0,%1,%2,%3};"
        : "+f"(c[0]), "+f"(c[1]), "+f"(c[2]), "+f"(c[3])
        : "r"(a0), "r"(a1), "r"(a2), "r"(a3), "r"(b0), "r"(b1));
}

#define R4V(v) v.x = __uint_as_float(f2tf(v.x)); v.y = __uint_as_float(f2tf(v.y)); \
               v.z = __uint_as_float(f2tf(v.z)); v.w = __uint_as_float(f2tf(v.w));

__global__ __launch_bounds__(256) void round_w4(
    const float* __restrict__ a, const float* __restrict__ b,
    const float* __restrict__ c, const float* __restrict__ d,
    float* __restrict__ oa, float* __restrict__ ob,
    float* __restrict__ oc, float* __restrict__ od)
{
    int i = blockIdx.x * 256 + threadIdx.x;
    float4 va = ((const float4*)a)[i]; R4V(va) ((float4*)oa)[i] = va;
    float4 vb = ((const float4*)b)[i]; R4V(vb) ((float4*)ob)[i] = vb;
    float4 vc = ((const float4*)c)[i]; R4V(vc) ((float4*)oc)[i] = vc;
    float4 vd = ((const float4*)d)[i]; R4V(vd) ((float4*)od)[i] = vd;
}

__global__ __launch_bounds__(256) void round_in3(
    const float* __restrict__ a, const float* __restrict__ b,
    const float* __restrict__ c,
    float* __restrict__ oa, float* __restrict__ ob, float* __restrict__ oc)
{
    int i = blockIdx.x * 256 + threadIdx.x;
    float4 va = ((const float4*)a)[i]; R4V(va) ((float4*)oa)[i] = va;
    float4 vb = ((const float4*)b)[i]; R4V(vb) ((float4*)ob)[i] = vb;
    float4 vc = ((const float4*)c)[i]; R4V(vc) ((float4*)oc)[i] = vc;
}

__global__ __launch_bounds__(256) void packb(
    const float* __restrict__ a, const float* __restrict__ b,
    const float* __restrict__ c, float* __restrict__ out)
{
    int i = blockIdx.x * 256 + threadIdx.x;         // < 3072
    int sel = i >> 10;
    const float* p = sel == 0 ? a : (sel == 1 ? b : c);
    out[i] = p[i & 1023];
}

// C = scale*A*op(B) + bias[bb*biasStride + col].
// NT=false: B [K,N] row-major (NN); NT=true: B [N,K] row-major (C = A B^T).
// z -> (bb = z/H, hh = z%H). All A/B data must already be tf32-rounded.
template <int BM, int BN, bool NT, int NTHREADS, bool ROUND, int STAGES>
__global__ __launch_bounds__(NTHREADS, 2) void gemm1x(
    const float* __restrict__ A, long long aB, long long aH, int lda,
    const float* __restrict__ Bmat, long long bB, long long bH, int ldb,
    float* __restrict__ C, long long cB, long long cH, int ldc,
    int K, const float* __restrict__ bias, long long biasStride,
    float scale, int H)
{
    constexpr int BK = 32;
    constexpr int WARPS_M = BM / 64;          // warp tile 64x32
    constexpr int AP  = 40;                   // LDS.64 conflict-free pad
    constexpr int BNP = BN + 4;
    constexpr int ASZ = BM * AP;
    constexpr int BSZ = NT ? BN * AP : BK * BNP;

    extern __shared__ float sm[];
    float* sA = sm;
    float* sB = sm + STAGES * ASZ;

    const int z  = blockIdx.z;
    const int bb = z / H, hh = z - bb * H;
    const float* Ap = A + (long long)bb * aB + (long long)hh * aH
                        + (long long)blockIdx.y * BM * lda;
    const float* Bp;
    if (NT) Bp = Bmat + (long long)bb * bB + (long long)hh * bH
                      + (long long)blockIdx.x * BN * ldb;
    else    Bp = Bmat + (long long)bb * bB + (long long)hh * bH
                      + (long long)blockIdx.x * BN;
    float* Cp = C + (long long)bb * cB + (long long)hh * cH;
    const float* bp = bias ? bias + (long long)bb * biasStride : nullptr;

    const int tid  = threadIdx.x;
    const int lane = tid & 31;
    const int wid  = tid >> 5;
    const int wm   = (wid % WARPS_M) * 64;
    const int wn   = (wid / WARPS_M) * 32;
    const int lq   = lane >> 2;               // 0..7
    const int lc   = lane & 3;                // 0..3

    float acc[4][4][4];
#pragma unroll
    for (int i = 0; i < 4; i++)
#pragma unroll
        for (int j = 0; j < 4; j++)
#pragma unroll
            for (int c = 0; c < 4; c++) acc[i][j][c] = 0.f;

    auto load_tile = [&](int slot, int k0) {
        float* dA = sA + slot * ASZ;
        float* dB = sB + slot * BSZ;
#pragma unroll
        for (int i = 0; i < (BM * 8) / NTHREADS; i++) {
            int t = tid + i * NTHREADS;
            int r = t >> 3, c4 = (t & 7) * 4;
            CP_ASYNC16(s2u(dA + r * AP + c4), Ap + (long long)r * lda + k0 + c4);
        }
        if (NT) {
#pragma unroll
            for (int i = 0; i < (BN * 8) / NTHREADS; i++) {
                int t = tid + i * NTHREADS;
                int r = t >> 3, c4 = (t & 7) * 4;
                CP_ASYNC16(s2u(dB + r * AP + c4), Bp + (long long)r * ldb + k0 + c4);
            }
        } else {
#pragma unroll
            for (int i = 0; i < (BN * 8) / NTHREADS; i++) {
                int t = tid + i * NTHREADS;
                constexpr int C4 = BN / 4;
                int r = t / C4, c4 = (t - r * C4) * 4;
                CP_ASYNC16(s2u(dB + r * BNP + c4), Bp + (long long)(k0 + r) * ldb + c4);
            }
        }
    };

    auto compute = [&](int slot) {
        const float* cA = sA + slot * ASZ;
        const float* cB = sB + slot * BSZ;
#pragma unroll
        for (int ks = 0; ks < 4; ks++) {
            const int kb = ks * 8;
            const int kk = kb + 2 * lc;       // thread's k-pair: kk, kk+1
            uint32_t a0[4], a1[4], a2[4], a3[4];
#pragma unroll
            for (int mt = 0; mt < 4; mt++) {
                int r = wm + mt * 16 + lq;
                float2 lo = *(const float2*)(cA + r * AP + kk);
                float2 hi = *(const float2*)(cA + (r + 8) * AP + kk);
                a0[mt] = __float_as_uint(lo.x);
                a2[mt] = __float_as_uint(lo.y);
                a1[mt] = __float_as_uint(hi.x);
                a3[mt] = __float_as_uint(hi.y);
            }
            uint32_t bh[4][2];
#pragma unroll
            for (int nt = 0; nt < 4; nt++) {
                int n = wn + nt * 8 + lq;
                if (NT) {
                    float2 bv = *(const float2*)(cB + n * AP + kk);
                    bh[nt][0] = __float_as_uint(bv.x);
                    bh[nt][1] = __float_as_uint(bv.y);
                } else {
                    bh[nt][0] = __float_as_uint(cB[kk * BNP + n]);
                    bh[nt][1] = __float_as_uint(cB[(kk + 1) * BNP + n]);
                }
            }
#pragma unroll
            for (int mt = 0; mt < 4; mt++)
#pragma unroll
                for (int nt = 0; nt < 4; nt++)
                    mma8(acc[mt][nt], a0[mt], a1[mt], a2[mt], a3[mt],
                         bh[nt][0], bh[nt][1]);
        }
    };

    const int kt_n = K / BK;
#pragma unroll
    for (int st = 0; st < STAGES - 1; st++) {
        if (st < kt_n) load_tile(st, st * BK);
        CP_COMMIT();
    }
    for (int kt = 0; kt < kt_n; kt++) {
        cp_wait<STAGES - 2>();
        __syncthreads();
        int nk = kt + STAGES - 1;
        if (nk < kt_n) load_tile(nk % STAGES, nk * BK);
        CP_COMMIT();
        compute(kt % STAGES);
    }

    const int row0 = blockIdx.y * BM + wm;
    const int col0 = blockIdx.x * BN + wn;
#pragma unroll
    for (int mt = 0; mt < 4; mt++) {
#pragma unroll
        for (int nt = 0; nt < 4; nt++) {
            int r = row0 + mt * 16 + lq;
            int c = col0 + nt * 8 + 2 * lc;
            float b0 = bp ? bp[c]     : 0.f;
            float b1 = bp ? bp[c + 1] : 0.f;
            float o0 = acc[mt][nt][0] * scale + b0;
            float o1 = acc[mt][nt][1] * scale + b1;
            float o2 = acc[mt][nt][2] * scale + b0;
            float o3 = acc[mt][nt][3] * scale + b1;
            if (ROUND) {
                o0 = __uint_as_float(f2tf(o0));
                o1 = __uint_as_float(f2tf(o1));
                o2 = __uint_as_float(f2tf(o2));
                o3 = __uint_as_float(f2tf(o3));
            }
            *(float2*)(Cp + (long long)r * ldc + c)       = make_float2(o0, o1);
            *(float2*)(Cp + (long long)(r + 8) * ldc + c) = make_float2(o2, o3);
        }
    }
}

// Block = one (b,q); mask row in smem; 16 warps = 16 heads.
// aw rounded to tf32 on store (it is the context GEMM's A operand).
__global__ __launch_bounds__(512) void softmax_rows(
    float* __restrict__ aw, const int* __restrict__ mask)
{
    __shared__ int smask[1024];
    const int bq = blockIdx.x;                 // b*1024 + q
    const int b  = bq >> 10, q = bq & 1023;
    const int* mrow = mask + ((long long)bq << 10);
    if (threadIdx.x < 256)
        ((int4*)smask)[threadIdx.x] = ((const int4*)mrow)[threadIdx.x];
    __syncthreads();

    const int h    = threadIdx.x >> 5;
    const int lane = threadIdx.x & 31;
    float* arow = aw + ((long long)((b * 16 + h) * 1024 + q) << 10);

    float v[32];
    float m = NEG_INF_F;
#pragma unroll
    for (int j = 0; j < 8; j++) {
        int c = (lane + 32 * j) * 4;
        float4 f = __ldcs((const float4*)(arow + c));
        int4  mk = *(const int4*)(smask + c);
        v[4 * j + 0] = mk.x ? f.x : NEG_INF_F;
        v[4 * j + 1] = mk.y ? f.y : NEG_INF_F;
        v[4 * j + 2] = mk.z ? f.z : NEG_INF_F;
        v[4 * j + 3] = mk.w ? f.w : NEG_INF_F;
        m = fmaxf(m, fmaxf(fmaxf(v[4 * j], v[4 * j + 1]),
                           fmaxf(v[4 * j + 2], v[4 * j + 3])));
    }
#pragma unroll
    for (int o = 16; o > 0; o >>= 1) m = fmaxf(m, __shfl_xor_sync(0xffffffffu, m, o));
    float s = 0.f;
#pragma unroll
    for (int i = 0; i < 32; i++) { float e = __expf(v[i] - m); v[i] = e; s += e; }
#pragma unroll
    for (int o = 16; o > 0; o >>= 1) s += __shfl_xor_sync(0xffffffffu, s, o);
    float inv = 1.f / s;
#pragma unroll
    for (int j = 0; j < 8; j++) {
        int c = (lane + 32 * j) * 4;
        float4 o4 = make_float4(v[4 * j] * inv, v[4 * j + 1] * inv,
                                v[4 * j + 2] * inv, v[4 * j + 3] * inv);
        R4V(o4)
        __stcs((float4*)(arow + c), o4);
    }
}

extern "C" void kernel_launch(void* const* d_in, const int* in_sizes, int n_in,
                              void* d_out, int out_size)
{
    const float* key   = (const float*)d_in[0];
    const float* value = (const float*)d_in[1];
    const float* query = (const float*)d_in[2];
    const int*   mask  = (const int*)d_in[3];
    const float* Wk = (const float*)d_in[4];
    const float* bk = (const float*)d_in[5];
    const float* Wv = (const float*)d_in[6];
    const float* bv = (const float*)d_in[7];
    const float* Wq = (const float*)d_in[8];
    const float* bq = (const float*)d_in[9];
    const float* Wo = (const float*)d_in[10];
    const float* bo = (const float*)d_in[11];

    float* cv = (float*)d_out;                    // [2, 1024, 1024]
    float* aw = cv + 2LL * 1024 * 1024;           // [2, 16, 1024, 1024]

    float *qkv, *rin, *w3, *wo3, *b3, *gc;
    cudaGetSymbolAddress((void**)&qkv, g_qkv);
    cudaGetSymbolAddress((void**)&rin, g_rin);
    cudaGetSymbolAddress((void**)&w3,  g_w);
    cudaGetSymbolAddress((void**)&wo3, g_wo);
    cudaGetSymbolAddress((void**)&b3,  g_b3);
    cudaGetSymbolAddress((void**)&gc,  g_ctx);

    // smem: NN128/3st = 3*(128*40 + 32*132)*4 = 112128   (x2 CTA = 224256)
    //       NT128/2st = 2*(128*40 + 128*40)*4 = 81920
    //       NN64 /3st = 3*(128*40 + 32*68)*4  = 87552
    cudaFuncSetAttribute((const void*)gemm1x<128, 128, false, 256, true, 3>,
                         cudaFuncAttributeMaxDynamicSharedMemorySize, 112128);
    cudaFuncSetAttribute((const void*)gemm1x<128, 128, true, 256, false, 2>,
                         cudaFuncAttributeMaxDynamicSharedMemorySize, 81920);
    cudaFuncSetAttribute((const void*)gemm1x<128, 64, false, 128, true, 3>,
                         cudaFuncAttributeMaxDynamicSharedMemorySize, 87552);
    cudaFuncSetAttribute((const void*)gemm1x<128, 64, false, 128, false, 3>,
                         cudaFuncAttributeMaxDynamicSharedMemorySize, 87552);

    const long long M2 = 2097152, M1 = 1048576;
    float* Qp = qkv;              // [2048,1024] rounded Q
    float* Kp = qkv + M2;         // [2048,1024] rounded K
    float* Vp = qkv + 2 * M2;     // [2048,1024] rounded V

    // 0) prep
    round_w4<<<1024, 256>>>(Wq, Wk, Wv, Wo, w3, w3 + M1, w3 + 2 * M1, wo3);
    round_in3<<<2048, 256>>>(query, key, value, rin, rin + M2, rin + 2 * M2);
    packb<<<12, 256>>>(bq, bk, bv, b3);

    // 1) fused projections: z=0,1,2 -> Q,K,V (outputs tf32-rounded)
    gemm1x<128, 128, false, 256, true, 3><<<dim3(8, 16, 3), 256, 112128>>>(
        rin, M2, 0, 1024,
        w3,  M1, 0, 1024,
        qkv, M2, 0, 1024,
        1024, b3, 1024, 1.f, 1);

    // 2) scores per (b,h): S = Q K^T / 8 -> aw raw fp32
    gemm1x<128, 128, true, 256, false, 2><<<dim3(8, 8, 32), 256, 81920>>>(
        Qp, M1, 64, 1024,
        Kp, M1, 64, 1024,
        aw, 16777216LL, 1048576LL, 1024,
        64, nullptr, 0, 0.125f, 16);

    // 3) masked softmax (block per (b,q)); aw rounded to tf32
    softmax_rows<<<2048, 512>>>(aw, mask);

    // 4) context per (b,h): ctx = aw @ V, rounded epilogue (no split-K)
    gemm1x<128, 64, false, 128, true, 3><<<dim3(1, 8, 32), 128, 87552>>>(
        aw, 16777216LL, 1048576LL, 1024,
        Vp, M1, 64, 1024,
        gc, M1, 64, 1024,
        1024, nullptr, 0, 1.f, 16);

    // 5) output projection: cv = ctx @ Wo + bo  (BN=64, grid 256)
    gemm1x<128, 64, false, 128, false, 3><<<dim3(16, 16, 1), 128, 87552>>>(
        gc,  0, 0, 1024,
        wo3, 0, 0, 1024,
        cv,  0, 0, 1024,
        1024, bo, 0, 1.f, 1);
}

// round 10
// speedup vs baseline: 1.2505x; 1.0071x over previous
#include <cuda_runtime.h>
#include <cstdint>

// ----------------------------------------------------------------------------
// MultiheadAttention forward — 1xTF32; NT GEMMs via transposed weights.
//   prep    : round inputs; transpose+round weights (W^T); pack biases
//   proj    : fused z=3 NT launch (A=rounded inputs, B=W^T), outputs rounded
//   scores  : per (b,h) S = Q K^T / 8 (NT, raw fp32)
//   softmax : block per (b,q), aw rounded to tf32 on store
//   context : per (b,h) ctx = aw @ V (NN, 256-thr blocks, warp tile 32x32)
//   outproj : NT (B=Wo^T), cv = ctx @ Wo + bo
// ----------------------------------------------------------------------------

#define NEG_INF_F (__int_as_float(0xff7fffff))   // -FLT_MAX

static __device__ float g_qkv[3 * 2048 * 1024];   // rounded Q,K,V projections
static __device__ float g_rin[3 * 2048 * 1024];   // rounded inputs q,k,v
static __device__ float g_w  [3 * 1024 * 1024];   // rounded Wq^T,Wk^T,Wv^T
static __device__ float g_wo [1024 * 1024];       // rounded Wo^T
static __device__ float g_b3 [3 * 1024];          // packed biases bq,bk,bv
static __device__ float g_ctx[2048 * 1024];

__device__ __forceinline__ uint32_t f2tf(float x) {
    uint32_t r;
    asm("cvt.rna.tf32.f32 %0, %1;" : "=r"(r) : "f"(x));
    return r;
}
__device__ __forceinline__ uint32_t s2u(const void* p) {
    return (uint32_t)__cvta_generic_to_shared(p);
}

#define CP_ASYNC16(dst, src) \
    asm volatile("cp.async.cg.shared.global [%0], [%1], 16;" :: "r"(dst), "l"(src))
#define CP_COMMIT() asm volatile("cp.async.commit_group;")
template <int N>
__device__ __forceinline__ void cp_wait() {
    asm volatile("cp.async.wait_group %0;" :: "n"(N));
}

__device__ __forceinline__ void mma8(float c[4], uint32_t a0, uint32_t a1,
                                     uint32_t a2, uint32_t a3,
                                     uint32_t b0, uint32_t b1) {
    asm volatile(
        "mma.sync.aligned.m16n8k8.row.col.f32.tf32.tf32.f32 "
        "{%0,%1,%2,%3},{%4,%5,%6,%7},{%8,%9},{%0,%1,%2,%3};"
        : "+f"(c[0]), "+f"(c[1]), "+f"(c[2]), "+f"(c[3])
        : "r"(a0), "r"(a1), "r"(a2), "r"(a3), "r"(b0), "r"(b1));
}

#define R4V(v) v.x = __uint_as_float(f2tf(v.x)); v.y = __uint_as_float(f2tf(v.y)); \
               v.z = __uint_as_float(f2tf(v.z)); v.w = __uint_as_float(f2tf(v.w));

// Transpose + round 4 weight matrices (1024x1024). grid (32,32,4), 256 thr.
__global__ __launch_bounds__(256) void trx_w(
    const float* __restrict__ a, const float* __restrict__ b,
    const float* __restrict__ c, const float* __restrict__ d,
    float* __restrict__ oa, float* __restrict__ ob,
    float* __restrict__ oc, float* __restrict__ od)
{
    __shared__ float t[32][33];
    const int z = blockIdx.z;
    const float* in  = z == 0 ? a : (z == 1 ? b : (z == 2 ? c : d));
    float*       out = z == 0 ? oa : (z == 1 ? ob : (z == 2 ? oc : od));
    const int bx = blockIdx.x * 32, by = blockIdx.y * 32;
    const int lx = threadIdx.x & 31, ly = threadIdx.x >> 5;   // ly 0..7
#pragma unroll
    for (int j = 0; j < 4; j++) {
        int r = ly + 8 * j;
        t[r][lx] = __uint_as_float(f2tf(in[(long long)(by + r) * 1024 + bx + lx]));
    }
    __syncthreads();
#pragma unroll
    for (int j = 0; j < 4; j++) {
        int r = ly + 8 * j;
        out[(long long)(bx + r) * 1024 + by + lx] = t[lx][r];
    }
}

__global__ __launch_bounds__(256) void round_in3(
    const float* __restrict__ a, const float* __restrict__ b,
    const float* __restrict__ c,
    float* __restrict__ oa, float* __restrict__ ob, float* __restrict__ oc)
{
    int i = blockIdx.x * 256 + threadIdx.x;
    float4 va = ((const float4*)a)[i]; R4V(va) ((float4*)oa)[i] = va;
    float4 vb = ((const float4*)b)[i]; R4V(vb) ((float4*)ob)[i] = vb;
    float4 vc = ((const float4*)c)[i]; R4V(vc) ((float4*)oc)[i] = vc;
}

__global__ __launch_bounds__(256) void packb(
    const float* __restrict__ a, const float* __restrict__ b,
    const float* __restrict__ c, float* __restrict__ out)
{
    int i = blockIdx.x * 256 + threadIdx.x;         // < 3072
    int sel = i >> 10;
    const float* p = sel == 0 ? a : (sel == 1 ? b : c);
    out[i] = p[i & 1023];
}

// C = scale*A*op(B) + bias[bb*biasStride + col].
// NT=false: B [K,N] row-major (NN); NT=true: B [N,K] row-major (C = A B^T).
// WTM: warp tile M (64 or 32); warp tile N fixed at 32.
// z -> (bb = z/H, hh = z%H). All A/B data must already be tf32-rounded.
template <int BM, int BN, int WTM, bool NT, int NTHREADS, bool ROUND, int STAGES>
__global__ __launch_bounds__(NTHREADS, 2) void gemmx(
    const float* __restrict__ A, long long aB, long long aH, int lda,
    const float* __restrict__ Bmat, long long bB, long long bH, int ldb,
    float* __restrict__ C, long long cB, long long cH, int ldc,
    int K, const float* __restrict__ bias, long long biasStride,
    float scale, int H)
{
    constexpr int BK = 32;
    constexpr int WARPS_M = BM / WTM;
    constexpr int MT = WTM / 16;
    constexpr int AP  = 40;                   // LDS.64 conflict-free pad
    constexpr int BNP = BN + 4;
    constexpr int ASZ = BM * AP;
    constexpr int BSZ = NT ? BN * AP : BK * BNP;

    extern __shared__ float sm[];
    float* sA = sm;
    float* sB = sm + STAGES * ASZ;

    const int z  = blockIdx.z;
    const int bb = z / H, hh = z - bb * H;
    const float* Ap = A + (long long)bb * aB + (long long)hh * aH
                        + (long long)blockIdx.y * BM * lda;
    const float* Bp;
    if (NT) Bp = Bmat + (long long)bb * bB + (long long)hh * bH
                      + (long long)blockIdx.x * BN * ldb;
    else    Bp = Bmat + (long long)bb * bB + (long long)hh * bH
                      + (long long)blockIdx.x * BN;
    float* Cp = C + (long long)bb * cB + (long long)hh * cH;
    const float* bp = bias ? bias + (long long)bb * biasStride : nullptr;

    const int tid  = threadIdx.x;
    const int lane = tid & 31;
    const int wid  = tid >> 5;
    const int wm   = (wid % WARPS_M) * WTM;
    const int wn   = (wid / WARPS_M) * 32;
    const int lq   = lane >> 2;               // 0..7
    const int lc   = lane & 3;                // 0..3

    float acc[MT][4][4];
#pragma unroll
    for (int i = 0; i < MT; i++)
#pragma unroll
        for (int j = 0; j < 4; j++)
#pragma unroll
            for (int c = 0; c < 4; c++) acc[i][j][c] = 0.f;

    auto load_tile = [&](int slot, int k0) {
        float* dA = sA + slot * ASZ;
        float* dB = sB + slot * BSZ;
#pragma unroll
        for (int i = 0; i < (BM * 8) / NTHREADS; i++) {
            int t = tid + i * NTHREADS;
            int r = t >> 3, c4 = (t & 7) * 4;
            CP_ASYNC16(s2u(dA + r * AP + c4), Ap + (long long)r * lda + k0 + c4);
        }
        if (NT) {
#pragma unroll
            for (int i = 0; i < (BN * 8) / NTHREADS; i++) {
                int t = tid + i * NTHREADS;
                int r = t >> 3, c4 = (t & 7) * 4;
                CP_ASYNC16(s2u(dB + r * AP + c4), Bp + (long long)r * ldb + k0 + c4);
            }
        } else {
#pragma unroll
            for (int i = 0; i < (BN * 8) / NTHREADS; i++) {
                int t = tid + i * NTHREADS;
                constexpr int C4 = BN / 4;
                int r = t / C4, c4 = (t - r * C4) * 4;
                CP_ASYNC16(s2u(dB + r * BNP + c4), Bp + (long long)(k0 + r) * ldb + c4);
            }
        }
    };

    auto compute = [&](int slot) {
        const float* cA = sA + slot * ASZ;
        const float* cB = sB + slot * BSZ;
#pragma unroll
        for (int ks = 0; ks < 4; ks++) {
            const int kb = ks * 8;
            const int kk = kb + 2 * lc;       // thread's k-pair: kk, kk+1
            uint32_t a0[MT], a1[MT], a2[MT], a3[MT];
#pragma unroll
            for (int mt = 0; mt < MT; mt++) {
                int r = wm + mt * 16 + lq;
                float2 lo = *(const float2*)(cA + r * AP + kk);
                float2 hi = *(const float2*)(cA + (r + 8) * AP + kk);
                a0[mt] = __float_as_uint(lo.x);
                a2[mt] = __float_as_uint(lo.y);
                a1[mt] = __float_as_uint(hi.x);
                a3[mt] = __float_as_uint(hi.y);
            }
            uint32_t bh[4][2];
#pragma unroll
            for (int nt = 0; nt < 4; nt++) {
                int n = wn + nt * 8 + lq;
                if (NT) {
                    float2 bv = *(const float2*)(cB + n * AP + kk);
                    bh[nt][0] = __float_as_uint(bv.x);
                    bh[nt][1] = __float_as_uint(bv.y);
                } else {
                    bh[nt][0] = __float_as_uint(cB[kk * BNP + n]);
                    bh[nt][1] = __float_as_uint(cB[(kk + 1) * BNP + n]);
                }
            }
#pragma unroll
            for (int mt = 0; mt < MT; mt++)
#pragma unroll
                for (int nt = 0; nt < 4; nt++)
                    mma8(acc[mt][nt], a0[mt], a1[mt], a2[mt], a3[mt],
                         bh[nt][0], bh[nt][1]);
        }
    };

    const int kt_n = K / BK;
#pragma unroll
    for (int st = 0; st < STAGES - 1; st++) {
        if (st < kt_n) load_tile(st, st * BK);
        CP_COMMIT();
    }
    for (int kt = 0; kt < kt_n; kt++) {
        cp_wait<STAGES - 2>();
        __syncthreads();
        int nk = kt + STAGES - 1;
        if (nk < kt_n) load_tile(nk % STAGES, nk * BK);
        CP_COMMIT();
        compute(kt % STAGES);
    }

    const int row0 = blockIdx.y * BM + wm;
    const int col0 = blockIdx.x * BN + wn;
#pragma unroll
    for (int mt = 0; mt < MT; mt++) {
#pragma unroll
        for (int nt = 0; nt < 4; nt++) {
            int r = row0 + mt * 16 + lq;
            int c = col0 + nt * 8 + 2 * lc;
            float b0 = bp ? bp[c]     : 0.f;
            float b1 = bp ? bp[c + 1] : 0.f;
            float o0 = acc[mt][nt][0] * scale + b0;
            float o1 = acc[mt][nt][1] * scale + b1;
            float o2 = acc[mt][nt][2] * scale + b0;
            float o3 = acc[mt][nt][3] * scale + b1;
            if (ROUND) {
                o0 = __uint_as_float(f2tf(o0));
                o1 = __uint_as_float(f2tf(o1));
                o2 = __uint_as_float(f2tf(o2));
                o3 = __uint_as_float(f2tf(o3));
            }
            *(float2*)(Cp + (long long)r * ldc + c)       = make_float2(o0, o1);
            *(float2*)(Cp + (long long)(r + 8) * ldc + c) = make_float2(o2, o3);
        }
    }
}

// Block = one (b,q); mask row in smem; 16 warps = 16 heads.
// aw rounded to tf32 on store (it is the context GEMM's A operand).
__global__ __launch_bounds__(512) void softmax_rows(
    float* __restrict__ aw, const int* __restrict__ mask)
{
    __shared__ int smask[1024];
    const int bq = blockIdx.x;                 // b*1024 + q
    const int b  = bq >> 10, q = bq & 1023;
    const int* mrow = mask + ((long long)bq << 10);
    if (threadIdx.x < 256)
        ((int4*)smask)[threadIdx.x] = ((const int4*)mrow)[threadIdx.x];
    __syncthreads();

    const int h    = threadIdx.x >> 5;
    const int lane = threadIdx.x & 31;
    float* arow = aw + ((long long)((b * 16 + h) * 1024 + q) << 10);

    float v[32];
    float m = NEG_INF_F;
#pragma unroll
    for (int j = 0; j < 8; j++) {
        int c = (lane + 32 * j) * 4;
        float4 f = __ldcs((const float4*)(arow + c));
        int4  mk = *(const int4*)(smask + c);
        v[4 * j + 0] = mk.x ? f.x : NEG_INF_F;
        v[4 * j + 1] = mk.y ? f.y : NEG_INF_F;
        v[4 * j + 2] = mk.z ? f.z : NEG_INF_F;
        v[4 * j + 3] = mk.w ? f.w : NEG_INF_F;
        m = fmaxf(m, fmaxf(fmaxf(v[4 * j], v[4 * j + 1]),
                           fmaxf(v[4 * j + 2], v[4 * j + 3])));
    }
#pragma unroll
    for (int o = 16; o > 0; o >>= 1) m = fmaxf(m, __shfl_xor_sync(0xffffffffu, m, o));
    float s = 0.f;
#pragma unroll
    for (int i = 0; i < 32; i++) { float e = __expf(v[i] - m); v[i] = e; s += e; }
#pragma unroll
    for (int o = 16; o > 0; o >>= 1) s += __shfl_xor_sync(0xffffffffu, s, o);
    float inv = 1.f / s;
#pragma unroll
    for (int j = 0; j < 8; j++) {
        int c = (lane + 32 * j) * 4;
        float4 o4 = make_float4(v[4 * j] * inv, v[4 * j + 1] * inv,
                                v[4 * j + 2] * inv, v[4 * j + 3] * inv);
        R4V(o4)
        __stcs((float4*)(arow + c), o4);
    }
}

extern "C" void kernel_launch(void* const* d_in, const int* in_sizes, int n_in,
                              void* d_out, int out_size)
{
    const float* key   = (const float*)d_in[0];
    const float* value = (const float*)d_in[1];
    const float* query = (const float*)d_in[2];
    const int*   mask  = (const int*)d_in[3];
    const float* Wk = (const float*)d_in[4];
    const float* bk = (const float*)d_in[5];
    const float* Wv = (const float*)d_in[6];
    const float* bv = (const float*)d_in[7];
    const float* Wq = (const float*)d_in[8];
    const float* bq = (const float*)d_in[9];
    const float* Wo = (const float*)d_in[10];
    const float* bo = (const float*)d_in[11];

    float* cv = (float*)d_out;                    // [2, 1024, 1024]
    float* aw = cv + 2LL * 1024 * 1024;           // [2, 16, 1024, 1024]

    float *qkv, *rin, *w3, *wo3, *b3, *gc;
    cudaGetSymbolAddress((void**)&qkv, g_qkv);
    cudaGetSymbolAddress((void**)&rin, g_rin);
    cudaGetSymbolAddress((void**)&w3,  g_w);
    cudaGetSymbolAddress((void**)&wo3, g_wo);
    cudaGetSymbolAddress((void**)&b3,  g_b3);
    cudaGetSymbolAddress((void**)&gc,  g_ctx);

    // smem: NT128/2st = 2*(128*40 + 128*40)*4 = 81920
    //       NN64 /3st = 3*(128*40 + 32*68)*4  = 87552   (ctx, 256 thr)
    //       NT64 /3st = 3*(128*40 + 64*40)*4  = 92160   (outproj, 128 thr)
    cudaFuncSetAttribute((const void*)gemmx<128, 128, 64, true, 256, true, 2>,
                         cudaFuncAttributeMaxDynamicSharedMemorySize, 81920);
    cudaFuncSetAttribute((const void*)gemmx<128, 128, 64, true, 256, false, 2>,
                         cudaFuncAttributeMaxDynamicSharedMemorySize, 81920);
    cudaFuncSetAttribute((const void*)gemmx<128, 64, 32, false, 256, true, 3>,
                         cudaFuncAttributeMaxDynamicSharedMemorySize, 87552);
    cudaFuncSetAttribute((const void*)gemmx<128, 64, 64, true, 128, false, 3>,
                         cudaFuncAttributeMaxDynamicSharedMemorySize, 92160);

    const long long M2 = 2097152, M1 = 1048576;
    float* Qp = qkv;              // [2048,1024] rounded Q
    float* Kp = qkv + M2;         // [2048,1024] rounded K
    float* Vp = qkv + 2 * M2;     // [2048,1024] rounded V

    // 0) prep: transpose+round weights; round inputs; pack biases
    trx_w<<<dim3(32, 32, 4), 256>>>(Wq, Wk, Wv, Wo,
                                    w3, w3 + M1, w3 + 2 * M1, wo3);
    round_in3<<<2048, 256>>>(query, key, value, rin, rin + M2, rin + 2 * M2);
    packb<<<12, 256>>>(bq, bk, bv, b3);

    // 1) fused projections (NT, B = W^T): z=0,1,2 -> Q,K,V (rounded outputs)
    gemmx<128, 128, 64, true, 256, true, 2><<<dim3(8, 16, 3), 256, 81920>>>(
        rin, M2, 0, 1024,
        w3,  M1, 0, 1024,
        qkv, M2, 0, 1024,
        1024, b3, 1024, 1.f, 1);

    // 2) scores per (b,h): S = Q K^T / 8 -> aw raw fp32
    gemmx<128, 128, 64, true, 256, false, 2><<<dim3(8, 8, 32), 256, 81920>>>(
        Qp, M1, 64, 1024,
        Kp, M1, 64, 1024,
        aw, 16777216LL, 1048576LL, 1024,
        64, nullptr, 0, 0.125f, 16);

    // 3) masked softmax (block per (b,q)); aw rounded to tf32
    softmax_rows<<<2048, 512>>>(aw, mask);

    // 4) context per (b,h): ctx = aw @ V (NN, 256 thr, warp tile 32x32)
    gemmx<128, 64, 32, false, 256, true, 3><<<dim3(1, 8, 32), 256, 87552>>>(
        aw, 16777216LL, 1048576LL, 1024,
        Vp, M1, 64, 1024,
        gc, M1, 64, 1024,
        1024, nullptr, 0, 1.f, 16);

    // 5) output projection (NT, B = Wo^T): cv = ctx @ Wo + bo
    gemmx<128, 64, 64, true, 128, false, 3><<<dim3(16, 16, 1), 128, 92160>>>(
        gc,  0, 0, 1024,
        wo3, 0, 0, 1024,
        cv,  0, 0, 1024,
        1024, bo, 0, 1.f, 1);
}